// round 2
// baseline (speedup 1.0000x reference)
#include <cuda_runtime.h>

#define B_ROWS 16384
#define HID 256
#define COMP 32
#define T_TOK 8
#define NVOC 257
#define NF 0.0625f
#define EPS_THR 1e-6f
#define NGROUP 2048

// ---------------- device scratch (no allocations allowed) ----------------
__device__ float g_Q[B_ROWS * HID];
__device__ float g_V[B_ROWS * HID];
__device__ float g_msg[B_ROWS * HID];
__device__ float g_mask[B_ROWS];
__device__ unsigned char g_fin[B_ROWS];
__device__ float g_T1[NGROUP * HID];

// ---------------- Kernel 1: Q = (hs@WQ+bQ)*NF, V = hs@WK+bK, init state ----
__global__ __launch_bounds__(256) void qv_kernel(
    const float* __restrict__ hs,
    const float* __restrict__ WQ, const float* __restrict__ bQ,
    const float* __restrict__ WK, const float* __restrict__ bK)
{
    __shared__ float A_s[32 * HID];
    const int t = threadIdx.x;
    const int r0 = blockIdx.x * 32;

    // load 32x256 fp32 tile (contiguous) as float4
    {
        const float4* src = (const float4*)(hs + (size_t)r0 * HID);
        float4* dst = (float4*)A_s;
        #pragma unroll
        for (int idx = t; idx < 32 * HID / 4; idx += 256) dst[idx] = src[idx];
    }
    if (t < 32) { g_mask[r0 + t] = 1.0f; g_fin[r0 + t] = 0; }
    __syncthreads();

    float accq[32], accv[32];
    const float bq = bQ[t], bk = bK[t];
    #pragma unroll
    for (int m = 0; m < 32; m++) { accq[m] = bq; accv[m] = bk; }

    const float4* A4 = (const float4*)A_s;
    for (int k = 0; k < HID; k += 4) {
        float q0 = WQ[(k + 0) * HID + t], q1 = WQ[(k + 1) * HID + t];
        float q2 = WQ[(k + 2) * HID + t], q3 = WQ[(k + 3) * HID + t];
        float v0 = WK[(k + 0) * HID + t], v1 = WK[(k + 1) * HID + t];
        float v2 = WK[(k + 2) * HID + t], v3 = WK[(k + 3) * HID + t];
        #pragma unroll
        for (int m = 0; m < 32; m++) {
            float4 a = A4[m * (HID / 4) + (k >> 2)];
            accq[m] += a.x * q0 + a.y * q1 + a.z * q2 + a.w * q3;
            accv[m] += a.x * v0 + a.y * v1 + a.z * v2 + a.w * v3;
        }
    }
    #pragma unroll
    for (int m = 0; m < 32; m++) {
        size_t o = (size_t)(r0 + m) * HID + t;
        g_Q[o] = accq[m] * NF;
        g_V[o] = accv[m];
        g_msg[o] = 0.0f;
    }
}

// ---------------- Kernel 2: one token-recurrence step (fused) --------------
// 16 rows per block, 256 threads. Dynamic smem layout (floats):
//   msg_s  [16*256]   offset 0
//   K_s    [16*256]   offset 4096   (reused in-place as hidden_attn)
//   voc_s  [257*32]   offset 8192
//   tok_s  [16*32]    offset 16416
//   maskf  [16]       offset 16928
//   total 16944 floats = 67776 bytes
__global__ __launch_bounds__(256) void iter_kernel(
    const float* __restrict__ WK, const float* __restrict__ bK,
    const float* __restrict__ Wmu, const float* __restrict__ bmu,
    const float* __restrict__ Wvar, const float* __restrict__ bvar,
    const float* __restrict__ vocab, const float* __restrict__ eps,
    int it)
{
    extern __shared__ float sm[];
    float* msg_s = sm;
    float* K_s   = sm + 4096;
    float* voc_s = sm + 8192;
    float* tok_s = sm + 16416;
    float* maskf = sm + 16928;

    const int t = threadIdx.x;
    const int r0 = blockIdx.x * 16;
    const int kc = it * COMP;   // only first it*32 message columns are nonzero

    for (int idx = t; idx < NVOC * COMP; idx += 256) voc_s[idx] = vocab[idx];
    if (t < kc) {
        #pragma unroll
        for (int m = 0; m < 16; m++)
            msg_s[m * HID + t] = g_msg[(size_t)(r0 + m) * HID + t];
    }
    if (t < 16) maskf[t] = g_mask[r0 + t];
    __syncthreads();

    // --- K = (msg @ WK + bK) * NF, thread t owns column t for 16 rows ---
    {
        float acc[16];
        const float bk = bK[t];
        #pragma unroll
        for (int m = 0; m < 16; m++) acc[m] = bk;
        for (int k = 0; k < kc; k += 4) {
            float w0 = WK[(k + 0) * HID + t], w1 = WK[(k + 1) * HID + t];
            float w2 = WK[(k + 2) * HID + t], w3 = WK[(k + 3) * HID + t];
            #pragma unroll
            for (int m = 0; m < 16; m++) {
                float4 a = ((const float4*)msg_s)[m * (HID / 4) + (k >> 2)];
                acc[m] += a.x * w0 + a.y * w1 + a.z * w2 + a.w * w3;
            }
        }
        #pragma unroll
        for (int m = 0; m < 16; m++) K_s[m * HID + t] = acc[m] * NF;
    }
    __syncthreads();

    // --- softmin over HID + hidden_attn = attn*V (overwrites K_s in place) ---
    {
        const int w = t >> 5, l = t & 31;
        #pragma unroll
        for (int mm = 0; mm < 2; mm++) {
            const int m = w * 2 + mm;
            const size_t r = (size_t)(r0 + m);
            float e[8]; float s = 0.0f;
            #pragma unroll
            for (int ss = 0; ss < 8; ss++) {
                int c = l + ss * 32;
                float q = g_Q[r * HID + c];
                float v = __expf(-(q * K_s[m * HID + c]));
                e[ss] = v; s += v;
            }
            #pragma unroll
            for (int o = 16; o > 0; o >>= 1) s += __shfl_xor_sync(0xffffffffu, s, o);
            const float inv = 1.0f / s;
            #pragma unroll
            for (int ss = 0; ss < 8; ss++) {
                int c = l + ss * 32;
                K_s[m * HID + c] = e[ss] * inv * g_V[r * HID + c];
            }
        }
    }
    __syncthreads();

    // --- mu/logvar GEMM + reparam sample + per-dim vocab min + mask ---
    {
        const int m = t >> 4;
        const int c0 = (t & 15) * 2;
        float amu0 = bmu[c0], amu1 = bmu[c0 + 1];
        float alv0 = bvar[c0], alv1 = bvar[c0 + 1];
        const float4* ha4 = (const float4*)(K_s + m * HID);
        for (int k = 0; k < HID; k += 4) {
            float4 a = ha4[k >> 2];
            float av[4] = {a.x, a.y, a.z, a.w};
            #pragma unroll
            for (int kk = 0; kk < 4; kk++) {
                float2 wm = *(const float2*)&Wmu[(k + kk) * COMP + c0];
                float2 wv = *(const float2*)&Wvar[(k + kk) * COMP + c0];
                amu0 += av[kk] * wm.x; amu1 += av[kk] * wm.y;
                alv0 += av[kk] * wv.x; alv1 += av[kk] * wv.y;
            }
        }
        const size_t r = (size_t)(r0 + m);
        const size_t eoff = ((size_t)it * B_ROWS + r) * COMP;
        float x0 = eps[eoff + c0]     * __expf(0.5f * alv0) + amu0;
        float x1 = eps[eoff + c0 + 1] * __expf(0.5f * alv1) + amu1;
        float d0 = 3.4e38f, d1 = 3.4e38f;
        #pragma unroll 4
        for (int v = 0; v < NVOC; v++) {
            float2 vv = *(const float2*)&voc_s[v * COMP + c0];
            float a0 = x0 - vv.x, a1 = x1 - vv.y;
            d0 = fminf(d0, a0 * a0);
            d1 = fminf(d1, a1 * a1);
        }
        const float mk = maskf[m];
        tok_s[m * COMP + c0]     = d0 * mk;
        tok_s[m * COMP + c0 + 1] = d1 * mk;
    }
    __syncthreads();

    // --- EOS / repeat-hit logic, finalize token, write message ---
    {
        const int w = t >> 5, l = t & 31;  // lane l == composition dim
        #pragma unroll
        for (int mm = 0; mm < 2; mm++) {
            const int m = w * 2 + mm;
            const size_t r = (size_t)(r0 + m);
            float tk = tok_s[m * COMP + l];
            float eosv = voc_s[256 * COMP + l];
            float de = tk - eosv;
            float se = de * de;
            #pragma unroll
            for (int o = 16; o > 0; o >>= 1) se += __shfl_xor_sync(0xffffffffu, se, o);
            bool hit = (se < EPS_THR);
            for (int p = 0; p < it; p++) {
                float dp = tk - msg_s[m * HID + p * COMP + l];
                float sp = dp * dp;
                #pragma unroll
                for (int o = 16; o > 0; o >>= 1) sp += __shfl_xor_sync(0xffffffffu, sp, o);
                hit = hit || (sp < EPS_THR);
            }
            unsigned char fin = g_fin[r];
            bool new_eos = hit && (fin == 0);
            float outv = new_eos ? eosv : tk;
            g_msg[r * HID + it * COMP + l] = outv;
            if (l == 0 && hit) { g_mask[r] = 0.0f; g_fin[r] = 1; }
        }
    }
}

// ---------------- Kernel 3: group sum /7, then @W_sum + b_sum --------------
__global__ __launch_bounds__(256) void sum_gemm_kernel(
    const float* __restrict__ Wsum, const float* __restrict__ bsum)
{
    __shared__ float A_s[16 * HID];
    const int t = threadIdx.x;
    const int g0 = blockIdx.x * 16;
    #pragma unroll
    for (int m = 0; m < 16; m++) {
        float s = 0.0f;
        #pragma unroll
        for (int a = 0; a < 8; a++)
            s += g_msg[(size_t)((g0 + m) * 8 + a) * HID + t];
        A_s[m * HID + t] = s * (1.0f / 7.0f);
    }
    __syncthreads();
    float acc[16];
    const float bb = bsum[t];
    #pragma unroll
    for (int m = 0; m < 16; m++) acc[m] = bb;
    for (int k = 0; k < HID; k += 4) {
        float w0 = Wsum[(k + 0) * HID + t], w1 = Wsum[(k + 1) * HID + t];
        float w2 = Wsum[(k + 2) * HID + t], w3 = Wsum[(k + 3) * HID + t];
        #pragma unroll
        for (int m = 0; m < 16; m++) {
            float4 a = ((const float4*)A_s)[m * (HID / 4) + (k >> 2)];
            acc[m] += a.x * w0 + a.y * w1 + a.z * w2 + a.w * w3;
        }
    }
    #pragma unroll
    for (int m = 0; m < 16; m++) g_T1[(size_t)(g0 + m) * HID + t] = acc[m];
}

// ---------------- Kernel 4: relu(T1@W_head+b_head), broadcast to 8 agents --
__global__ __launch_bounds__(256) void head_kernel(
    const float* __restrict__ Whead, const float* __restrict__ bhead,
    float* __restrict__ out)
{
    __shared__ float A_s[16 * HID];
    const int t = threadIdx.x;
    const int g0 = blockIdx.x * 16;
    for (int idx = t; idx < 16 * HID; idx += 256)
        A_s[idx] = g_T1[(size_t)g0 * HID + idx];
    __syncthreads();
    float acc[16];
    const float bb = bhead[t];
    #pragma unroll
    for (int m = 0; m < 16; m++) acc[m] = bb;
    for (int k = 0; k < HID; k += 4) {
        float w0 = Whead[(k + 0) * HID + t], w1 = Whead[(k + 1) * HID + t];
        float w2 = Whead[(k + 2) * HID + t], w3 = Whead[(k + 3) * HID + t];
        #pragma unroll
        for (int m = 0; m < 16; m++) {
            float4 a = ((const float4*)A_s)[m * (HID / 4) + (k >> 2)];
            acc[m] += a.x * w0 + a.y * w1 + a.z * w2 + a.w * w3;
        }
    }
    #pragma unroll
    for (int m = 0; m < 16; m++) {
        float v = fmaxf(acc[m], 0.0f);
        #pragma unroll
        for (int a = 0; a < 8; a++)
            out[(size_t)((g0 + m) * 8 + a) * HID + t] = v;
    }
}

// ---------------- launch ---------------------------------------------------
extern "C" void kernel_launch(void* const* d_in, const int* in_sizes, int n_in,
                              void* d_out, int out_size)
{
    const float* hs    = (const float*)d_in[0];
    const float* eps   = (const float*)d_in[1];
    const float* WQ    = (const float*)d_in[2];
    const float* bQ    = (const float*)d_in[3];
    const float* WK    = (const float*)d_in[4];
    const float* bK    = (const float*)d_in[5];
    const float* Wmu   = (const float*)d_in[6];
    const float* bmu   = (const float*)d_in[7];
    const float* Wvar  = (const float*)d_in[8];
    const float* bvar  = (const float*)d_in[9];
    const float* vocab = (const float*)d_in[10];
    const float* Wsum  = (const float*)d_in[11];
    const float* bsum  = (const float*)d_in[12];
    const float* Whead = (const float*)d_in[13];
    const float* bhead = (const float*)d_in[14];
    float* out = (float*)d_out;

    const int smem_iter = 16944 * (int)sizeof(float);   // 67776 B
    cudaFuncSetAttribute(iter_kernel,
                         cudaFuncAttributeMaxDynamicSharedMemorySize, smem_iter);

    qv_kernel<<<B_ROWS / 32, 256>>>(hs, WQ, bQ, WK, bK);
    for (int i = 0; i < T_TOK; i++)
        iter_kernel<<<B_ROWS / 16, 256, smem_iter>>>(WK, bK, Wmu, bmu,
                                                     Wvar, bvar, vocab, eps, i);
    sum_gemm_kernel<<<NGROUP / 16, 256>>>(Wsum, bsum);
    head_kernel<<<NGROUP / 16, 256>>>(Whead, bhead, out);
}

// round 3
// speedup vs baseline: 2.5473x; 2.5473x over previous
#include <cuda_runtime.h>

#define B_ROWS 16384
#define HID 256
#define COMP 32
#define T_TOK 8
#define NVOC 257
#define VSTRIDE 261          // padded row stride for sorted vocab (bank-spread)
#define NF 0.0625f
#define EPS_THR 1e-6f
#define NGROUP 2048
#define ROWS_PB 16

// ---------------- device scratch (no allocations allowed) ----------------
__device__ float g_msg[B_ROWS * HID];
__device__ float g_vocs[COMP * VSTRIDE];   // per-dim sorted vocab columns

// ---------------- Kernel 0: per-dim bitonic sort of vocab columns ---------
// one block per dim; sorts 257 values (padded to 512 with +1e30)
__global__ __launch_bounds__(256) void sort_kernel(const float* __restrict__ vocab)
{
    __shared__ float buf[512];
    const int d = blockIdx.x;
    const int t = threadIdx.x;
    for (int i = t; i < 512; i += 256)
        buf[i] = (i < NVOC) ? vocab[i * COMP + d] : 1e30f;
    __syncthreads();
    for (int k = 2; k <= 512; k <<= 1) {
        for (int j = k >> 1; j > 0; j >>= 1) {
            for (int i = t; i < 512; i += 256) {
                int ixj = i ^ j;
                if (ixj > i) {
                    float a = buf[i], b = buf[ixj];
                    bool up = ((i & k) == 0);
                    if ((a > b) == up) { buf[i] = b; buf[ixj] = a; }
                }
            }
            __syncthreads();
        }
    }
    for (int i = t; i < NVOC; i += 256)
        g_vocs[d * VSTRIDE + i] = buf[i];
}

// branchless lower-bound nearest-neighbor squared distance.
// min over all v of (x-v)^2 == min over the two bracketing sorted values
// (fp subtraction and squaring are monotone in |x-v| per side) -> bitwise
// identical to the full 257-entry scan.
__device__ __forceinline__ float nearest_sq(const float* __restrict__ arr, float x)
{
    int p = 0;
    #pragma unroll
    for (int s = 256; s; s >>= 1) {
        int q = p + s;
        if (q <= NVOC) { if (arr[q - 1] <= x) p = q; }
    }
    float lo = (p > 0)    ? arr[p - 1] : 1e30f;
    float hi = (p < NVOC) ? arr[p]     : 1e30f;
    float a = x - lo, b = x - hi;
    return fminf(a * a, b * b);
}

// ---------------- Kernel 1: persistent fused main kernel -------------------
// 16 rows/block, 256 threads. smem (floats):
//   ha_s   [16*256] 0      (hs tile at init; e*V per iter; GEMM-partial staging)
//   msg_s  [16*256] 4096
//   vocs_s [32*261] 8192
//   mulv_s [16*64]  16544
//   tok_s  [16*32]  17568
//   eos_s  [32]     18080
//   maskf  [16]     18112
//   fin_s  [16]     18128
//   inv_s  [16]     18144
//   part_s [16*8]   18160
// total 18288 floats = 73152 B  -> 3 blocks/SM
__global__ void __launch_bounds__(256, 3) main_kernel(
    const float* __restrict__ hs,
    const float* __restrict__ WQ, const float* __restrict__ bQ,
    const float* __restrict__ WK, const float* __restrict__ bK,
    const float* __restrict__ Wmu, const float* __restrict__ bmu,
    const float* __restrict__ Wvar, const float* __restrict__ bvar,
    const float* __restrict__ vocab, const float* __restrict__ eps)
{
    extern __shared__ float sm[];
    float* ha_s   = sm;
    float* msg_s  = sm + 4096;
    float* vocs_s = sm + 8192;
    float* mulv_s = sm + 16544;
    float* tok_s  = sm + 17568;
    float* eos_s  = sm + 18080;
    float* maskf  = sm + 18112;
    float* fin_s  = sm + 18128;
    float* inv_s  = sm + 18144;
    float* part_s = sm + 18160;

    const int t = threadIdx.x;
    const int r0 = blockIdx.x * ROWS_PB;
    const int w = t >> 5, l = t & 31;

    // ---- block-resident setup ----
    for (int i = t; i < COMP * VSTRIDE; i += 256) vocs_s[i] = g_vocs[i];
    if (t < COMP) eos_s[t] = vocab[256 * COMP + t];
    if (t < ROWS_PB) { maskf[t] = 1.0f; fin_s[t] = 0.0f; }
    {
        const float4* src = (const float4*)(hs + (size_t)r0 * HID);
        float4* dst = (float4*)ha_s;
        for (int i = t; i < ROWS_PB * HID / 4; i += 256) dst[i] = src[i];
    }
    __syncthreads();

    // ---- Q = (hs@WQ+bQ)*NF ; V = hs@WK+bK ; kacc = msg@WK+bK (=bK) ----
    float Qr[16], Vr[16], kacc[16];
    {
        const float bq = bQ[t], bk = bK[t];
        #pragma unroll
        for (int m = 0; m < 16; m++) { Qr[m] = bq; Vr[m] = bk; }
        #pragma unroll 2
        for (int k = 0; k < HID; k += 4) {
            float q0 = WQ[(k+0)*HID+t], q1 = WQ[(k+1)*HID+t];
            float q2 = WQ[(k+2)*HID+t], q3 = WQ[(k+3)*HID+t];
            float v0 = WK[(k+0)*HID+t], v1 = WK[(k+1)*HID+t];
            float v2 = WK[(k+2)*HID+t], v3 = WK[(k+3)*HID+t];
            #pragma unroll
            for (int m = 0; m < 16; m++) {
                float4 a = ((const float4*)ha_s)[m * (HID/4) + (k >> 2)];
                Qr[m] += a.x*q0 + a.y*q1 + a.z*q2 + a.w*q3;
                Vr[m] += a.x*v0 + a.y*v1 + a.z*v2 + a.w*v3;
            }
        }
        #pragma unroll
        for (int m = 0; m < 16; m++) { Qr[m] *= NF; kacc[m] = bk; }
    }

    // ---- token recurrence ----
    #pragma unroll 1
    for (int it = 0; it < T_TOK; it++) {
        __syncthreads();

        // Phase 1: incremental K update with previous token (32 new msg cols)
        if (it > 0) {
            const float* wkp = WK + (size_t)((it - 1) * COMP) * HID + t;
            #pragma unroll 2
            for (int c = 0; c < 8; c++) {
                float w0 = wkp[(c*4+0)*HID], w1 = wkp[(c*4+1)*HID];
                float w2 = wkp[(c*4+2)*HID], w3 = wkp[(c*4+3)*HID];
                #pragma unroll
                for (int m = 0; m < 16; m++) {
                    float4 tk = ((const float4*)tok_s)[m * 8 + c];
                    kacc[m] += tk.x*w0 + tk.y*w1 + tk.z*w2 + tk.w*w3;
                }
            }
        }

        // Phase 2: e = exp(-(Q*K)); write e*V to ha_s; per-row partial sums
        #pragma unroll
        for (int m = 0; m < 16; m++) {
            float e = __expf(-(Qr[m] * (kacc[m] * NF)));
            ha_s[m * HID + t] = e * Vr[m];
            float s = e;
            #pragma unroll
            for (int o = 16; o; o >>= 1) s += __shfl_xor_sync(0xffffffffu, s, o);
            if (l == 0) part_s[m * 8 + w] = s;
        }
        __syncthreads();
        if (t < 16) {
            float s = 0.0f;
            #pragma unroll
            for (int ww = 0; ww < 8; ww++) s += part_s[t * 8 + ww];
            inv_s[t] = 1.0f / s;
        }
        __syncthreads();

        // Phase 3a: raw (e*V) @ [Wmu|Wvar] -- thread owns 1 output col for all
        // 16 rows over a 64-wide k-partition (weights loaded ONCE, reused x16)
        {
            const int c  = t & 63;        // 0..31 -> Wmu col c, 32..63 -> Wvar col c-32
            const int kp = t >> 6;        // 0..3
            const float* Wcol = (c < 32) ? (Wmu + c) : (Wvar + (c - 32));
            float acc[16];
            #pragma unroll
            for (int m = 0; m < 16; m++) acc[m] = 0.0f;
            const int k0 = kp * 64;
            #pragma unroll 2
            for (int k = k0; k < k0 + 64; k += 4) {
                float w0 = Wcol[(size_t)(k+0)*COMP], w1 = Wcol[(size_t)(k+1)*COMP];
                float w2 = Wcol[(size_t)(k+2)*COMP], w3 = Wcol[(size_t)(k+3)*COMP];
                #pragma unroll
                for (int m = 0; m < 16; m++) {
                    float4 a = ((const float4*)ha_s)[m * (HID/4) + (k >> 2)];
                    acc[m] += a.x*w0 + a.y*w1 + a.z*w2 + a.w*w3;
                }
            }
            __syncthreads();   // all ha_s reads done -> safe to overwrite as staging
            #pragma unroll
            for (int m = 0; m < 16; m++) ha_s[kp * 1024 + m * 64 + c] = acc[m];
        }
        __syncthreads();
        // reduce 4 k-partitions -> mulv_s[m][c]
        {
            float4 s = ((const float4*)ha_s)[t];
            #pragma unroll
            for (int kp = 1; kp < 4; kp++) {
                float4 b = ((const float4*)ha_s)[kp * 256 + t];
                s.x += b.x; s.y += b.y; s.z += b.z; s.w += b.w;
            }
            ((float4*)mulv_s)[t] = s;
        }
        __syncthreads();

        // Phase 3b: normalize, bias, sample, nearest-vocab sq dist, mask
        {
            const int m  = t >> 4;
            const int c0 = (t & 15) * 2;
            const float iv = inv_s[m];
            float2 rmu = *(const float2*)&mulv_s[m * 64 + c0];
            float2 rlv = *(const float2*)&mulv_s[m * 64 + 32 + c0];
            float2 bm  = *(const float2*)&bmu[c0];
            float2 bv  = *(const float2*)&bvar[c0];
            float amu0 = rmu.x * iv + bm.x, amu1 = rmu.y * iv + bm.y;
            float alv0 = rlv.x * iv + bv.x, alv1 = rlv.y * iv + bv.y;
            const size_t r = (size_t)(r0 + m);
            const float* ep = eps + ((size_t)it * B_ROWS + r) * COMP + c0;
            float2 e2 = *(const float2*)ep;
            float x0 = e2.x * __expf(0.5f * alv0) + amu0;
            float x1 = e2.y * __expf(0.5f * alv1) + amu1;
            float d0 = nearest_sq(vocs_s + c0 * VSTRIDE, x0);
            float d1 = nearest_sq(vocs_s + (c0 + 1) * VSTRIDE, x1);
            const float mk = maskf[m];
            tok_s[m * COMP + c0]     = d0 * mk;
            tok_s[m * COMP + c0 + 1] = d1 * mk;
        }
        __syncthreads();

        // Phase 4: EOS / repeat-hit logic -> final token into tok_s + msg_s
        {
            #pragma unroll
            for (int mm = 0; mm < 2; mm++) {
                const int m = w * 2 + mm;
                float tk = tok_s[m * COMP + l];
                float ev = eos_s[l];
                float de = tk - ev;
                float se = de * de;
                #pragma unroll
                for (int o = 16; o; o >>= 1) se += __shfl_xor_sync(0xffffffffu, se, o);
                bool hit = (se < EPS_THR);
                for (int p = 0; p < it; p++) {
                    float dp = tk - msg_s[m * HID + p * COMP + l];
                    float sp = dp * dp;
                    #pragma unroll
                    for (int o = 16; o; o >>= 1) sp += __shfl_xor_sync(0xffffffffu, sp, o);
                    hit = hit || (sp < EPS_THR);
                }
                float fin = fin_s[m];
                bool new_eos = hit && (fin == 0.0f);
                float outv = new_eos ? ev : tk;
                msg_s[m * HID + it * COMP + l] = outv;
                tok_s[m * COMP + l] = outv;
                if (l == 0 && hit) { maskf[m] = 0.0f; fin_s[m] = 1.0f; }
            }
        }
    }

    // ---- flush message to global for the tail ----
    __syncthreads();
    {
        float4* dst = (float4*)(g_msg + (size_t)r0 * HID);
        const float4* src = (const float4*)msg_s;
        for (int i = t; i < ROWS_PB * HID / 4; i += 256) dst[i] = src[i];
    }
}

// ---------------- Kernel 2: fused tail: group-sum/7 @Wsum -> @Whead+relu ---
__global__ __launch_bounds__(256) void tail_kernel(
    const float* __restrict__ Wsum, const float* __restrict__ bsum,
    const float* __restrict__ Whead, const float* __restrict__ bhead,
    float* __restrict__ out)
{
    __shared__ float A_s[16 * HID];
    const int t = threadIdx.x;
    const int g0 = blockIdx.x * 16;

    #pragma unroll
    for (int m = 0; m < 16; m++) {
        float s = 0.0f;
        #pragma unroll
        for (int a = 0; a < 8; a++)
            s += g_msg[(size_t)((g0 + m) * 8 + a) * HID + t];
        A_s[m * HID + t] = s * (1.0f / 7.0f);
    }
    __syncthreads();

    float acc[16];
    {
        const float bb = bsum[t];
        #pragma unroll
        for (int m = 0; m < 16; m++) acc[m] = bb;
        #pragma unroll 2
        for (int k = 0; k < HID; k += 4) {
            float w0 = Wsum[(k+0)*HID+t], w1 = Wsum[(k+1)*HID+t];
            float w2 = Wsum[(k+2)*HID+t], w3 = Wsum[(k+3)*HID+t];
            #pragma unroll
            for (int m = 0; m < 16; m++) {
                float4 a = ((const float4*)A_s)[m * (HID/4) + (k >> 2)];
                acc[m] += a.x*w0 + a.y*w1 + a.z*w2 + a.w*w3;
            }
        }
    }
    __syncthreads();
    #pragma unroll
    for (int m = 0; m < 16; m++) A_s[m * HID + t] = acc[m];
    __syncthreads();

    {
        const float bb = bhead[t];
        #pragma unroll
        for (int m = 0; m < 16; m++) acc[m] = bb;
        #pragma unroll 2
        for (int k = 0; k < HID; k += 4) {
            float w0 = Whead[(k+0)*HID+t], w1 = Whead[(k+1)*HID+t];
            float w2 = Whead[(k+2)*HID+t], w3 = Whead[(k+3)*HID+t];
            #pragma unroll
            for (int m = 0; m < 16; m++) {
                float4 a = ((const float4*)A_s)[m * (HID/4) + (k >> 2)];
                acc[m] += a.x*w0 + a.y*w1 + a.z*w2 + a.w*w3;
            }
        }
    }
    #pragma unroll
    for (int m = 0; m < 16; m++) {
        float v = fmaxf(acc[m], 0.0f);
        #pragma unroll
        for (int a = 0; a < 8; a++)
            out[(size_t)((g0 + m) * 8 + a) * HID + t] = v;
    }
}

// ---------------- launch ---------------------------------------------------
extern "C" void kernel_launch(void* const* d_in, const int* in_sizes, int n_in,
                              void* d_out, int out_size)
{
    const float* hs    = (const float*)d_in[0];
    const float* eps   = (const float*)d_in[1];
    const float* WQ    = (const float*)d_in[2];
    const float* bQ    = (const float*)d_in[3];
    const float* WK    = (const float*)d_in[4];
    const float* bK    = (const float*)d_in[5];
    const float* Wmu   = (const float*)d_in[6];
    const float* bmu   = (const float*)d_in[7];
    const float* Wvar  = (const float*)d_in[8];
    const float* bvar  = (const float*)d_in[9];
    const float* vocab = (const float*)d_in[10];
    const float* Wsum  = (const float*)d_in[11];
    const float* bsum  = (const float*)d_in[12];
    const float* Whead = (const float*)d_in[13];
    const float* bhead = (const float*)d_in[14];
    float* out = (float*)d_out;

    const int smem_main = 18288 * (int)sizeof(float);   // 73152 B
    cudaFuncSetAttribute(main_kernel,
                         cudaFuncAttributeMaxDynamicSharedMemorySize, smem_main);

    sort_kernel<<<COMP, 256>>>(vocab);
    main_kernel<<<B_ROWS / ROWS_PB, 256, smem_main>>>(
        hs, WQ, bQ, WK, bK, Wmu, bmu, Wvar, bvar, vocab, eps);
    tail_kernel<<<NGROUP / 16, 256>>>(Wsum, bsum, Whead, bhead, out);
}

// round 4
// speedup vs baseline: 2.8421x; 1.1158x over previous
#include <cuda_runtime.h>

#define B_ROWS 16384
#define HID 256
#define COMP 32
#define T_TOK 8
#define NVOC 257
#define VSTRIDE 261          // padded row stride for sorted vocab (bank-spread)
#define NF 0.0625f
#define EPS_THR 1e-6f
#define NGROUP 2048
#define ROWS_PB 16

typedef unsigned long long u64;

// ---- packed fp32x2 helpers (sm_103a FFMA2 path; ptxas never auto-fuses) ----
__device__ __forceinline__ u64 pk(float lo, float hi) {
    u64 r; asm("mov.b64 %0,{%1,%2};" : "=l"(r) : "f"(lo), "f"(hi)); return r;
}
__device__ __forceinline__ void ffma2(u64& d, u64 a, u64 b) {
    asm("fma.rn.f32x2 %0,%1,%2,%0;" : "+l"(d) : "l"(a), "l"(b));
}
__device__ __forceinline__ float upk_sum(u64 v) {
    float lo, hi; asm("mov.b64 {%0,%1},%2;" : "=f"(lo), "=f"(hi) : "l"(v));
    return lo + hi;
}
// one LDS.128 -> two packed f32x2 operands, no pack MOVs
__device__ __forceinline__ void lds2(u64& a, u64& b, unsigned addr) {
    asm("ld.shared.v2.u64 {%0,%1},[%2];" : "=l"(a), "=l"(b) : "r"(addr));
}

// ---------------- device scratch (no allocations allowed) ----------------
__device__ float g_msg[B_ROWS * HID];
__device__ float g_vocs[COMP * VSTRIDE];   // per-dim sorted vocab columns

// ---------------- Kernel 0: per-dim bitonic sort of vocab columns ---------
__global__ __launch_bounds__(512) void sort_kernel(const float* __restrict__ vocab)
{
    __shared__ float buf[512];
    const int d = blockIdx.x;
    const int t = threadIdx.x;
    buf[t] = (t < NVOC) ? vocab[t * COMP + d] : 1e30f;
    __syncthreads();
    for (int k = 2; k <= 512; k <<= 1) {
        for (int j = k >> 1; j > 0; j >>= 1) {
            int ixj = t ^ j;
            if (ixj > t) {
                float a = buf[t], b = buf[ixj];
                bool up = ((t & k) == 0);
                if ((a > b) == up) { buf[t] = b; buf[ixj] = a; }
            }
            __syncthreads();
        }
    }
    if (t < NVOC) g_vocs[d * VSTRIDE + t] = buf[t];
}

// branchless lower-bound nearest-neighbor squared distance (bitwise identical
// to the full 257-entry per-dim min scan; see round-2 derivation).
__device__ __forceinline__ float nearest_sq(const float* __restrict__ arr, float x)
{
    int p = 0;
    #pragma unroll
    for (int s = 256; s; s >>= 1) {
        int q = p + s;
        if (q <= NVOC) { if (arr[q - 1] <= x) p = q; }
    }
    float lo = (p > 0)    ? arr[p - 1] : 1e30f;
    float hi = (p < NVOC) ? arr[p]     : 1e30f;
    float a = x - lo, b = x - hi;
    return fminf(a * a, b * b);
}

// ---------------- Kernel 1: persistent fused main kernel -------------------
// 16 rows/block, 256 threads, 2 blocks/SM (128-reg budget, no spills).
// smem layout identical to round 2: 18288 floats = 73152 B.
__global__ void __launch_bounds__(256, 2) main_kernel(
    const float* __restrict__ hs,
    const float* __restrict__ WQ, const float* __restrict__ bQ,
    const float* __restrict__ WK, const float* __restrict__ bK,
    const float* __restrict__ Wmu, const float* __restrict__ bmu,
    const float* __restrict__ Wvar, const float* __restrict__ bvar,
    const float* __restrict__ vocab, const float* __restrict__ eps)
{
    extern __shared__ float sm[];
    float* ha_s   = sm;
    float* msg_s  = sm + 4096;
    float* vocs_s = sm + 8192;
    float* mulv_s = sm + 16544;
    float* tok_s  = sm + 17568;
    float* eos_s  = sm + 18080;
    float* maskf  = sm + 18112;
    float* fin_s  = sm + 18128;
    float* inv_s  = sm + 18144;
    float* part_s = sm + 18160;

    const int t = threadIdx.x;
    const int r0 = blockIdx.x * ROWS_PB;
    const int w = t >> 5, l = t & 31;
    const unsigned ha_sa  = (unsigned)__cvta_generic_to_shared(ha_s);
    const unsigned tok_sa = (unsigned)__cvta_generic_to_shared(tok_s);

    // ---- block-resident setup ----
    for (int i = t; i < COMP * VSTRIDE; i += 256) vocs_s[i] = g_vocs[i];
    if (t < COMP) eos_s[t] = vocab[256 * COMP + t];
    if (t < ROWS_PB) { maskf[t] = 1.0f; fin_s[t] = 0.0f; }
    {
        const float4* src = (const float4*)(hs + (size_t)r0 * HID);
        float4* dst = (float4*)ha_s;
        for (int i = t; i < ROWS_PB * HID / 4; i += 256) dst[i] = src[i];
    }
    __syncthreads();

    // ---- Q = (hs@WQ+bQ)*NF ; V = hs@WK+bK  (packed FFMA2 GEMM) ----
    float Qr[16], Vr[16], kacc[16];
    {
        const float bq = bQ[t], bk = bK[t];
        u64 aq[16], av[16];
        #pragma unroll
        for (int m = 0; m < 16; m++) { aq[m] = pk(bq, 0.0f); av[m] = pk(bk, 0.0f); }
        #pragma unroll 2
        for (int k = 0; k < HID; k += 4) {
            float q0 = WQ[(k+0)*HID+t], q1 = WQ[(k+1)*HID+t];
            float q2 = WQ[(k+2)*HID+t], q3 = WQ[(k+3)*HID+t];
            float v0 = WK[(k+0)*HID+t], v1 = WK[(k+1)*HID+t];
            float v2 = WK[(k+2)*HID+t], v3 = WK[(k+3)*HID+t];
            u64 wq01 = pk(q0, q1), wq23 = pk(q2, q3);
            u64 wv01 = pk(v0, v1), wv23 = pk(v2, v3);
            #pragma unroll
            for (int m = 0; m < 16; m++) {
                u64 a01, a23;
                lds2(a01, a23, ha_sa + (unsigned)((m * HID + k) * 4));
                ffma2(aq[m], a01, wq01); ffma2(aq[m], a23, wq23);
                ffma2(av[m], a01, wv01); ffma2(av[m], a23, wv23);
            }
        }
        #pragma unroll
        for (int m = 0; m < 16; m++) {
            Qr[m] = upk_sum(aq[m]) * NF;
            Vr[m] = upk_sum(av[m]);
            kacc[m] = bk;
        }
    }

    // ---- token recurrence ----
    #pragma unroll 1
    for (int it = 0; it < T_TOK; it++) {
        __syncthreads();

        // Phase 1: incremental K update with previous token (32 new msg cols)
        if (it > 0) {
            const float* wkp = WK + (size_t)((it - 1) * COMP) * HID + t;
            u64 acc2[16];
            #pragma unroll
            for (int m = 0; m < 16; m++) acc2[m] = 0ull;
            #pragma unroll
            for (int c = 0; c < COMP; c += 4) {
                float w0 = wkp[(c+0)*HID], w1 = wkp[(c+1)*HID];
                float w2 = wkp[(c+2)*HID], w3 = wkp[(c+3)*HID];
                u64 w01 = pk(w0, w1), w23 = pk(w2, w3);
                #pragma unroll
                for (int m = 0; m < 16; m++) {
                    u64 a01, a23;
                    lds2(a01, a23, tok_sa + (unsigned)((m * COMP + c) * 4));
                    ffma2(acc2[m], a01, w01); ffma2(acc2[m], a23, w23);
                }
            }
            #pragma unroll
            for (int m = 0; m < 16; m++) kacc[m] += upk_sum(acc2[m]);
        }

        // Phase 2: e = exp(-(Q*K)); write e*V to ha_s; per-row partial sums
        #pragma unroll
        for (int m = 0; m < 16; m++) {
            float e = __expf(-(Qr[m] * (kacc[m] * NF)));
            ha_s[m * HID + t] = e * Vr[m];
            float s = e;
            #pragma unroll
            for (int o = 16; o; o >>= 1) s += __shfl_xor_sync(0xffffffffu, s, o);
            if (l == 0) part_s[m * 8 + w] = s;
        }
        __syncthreads();
        if (t < 16) {
            float s = 0.0f;
            #pragma unroll
            for (int ww = 0; ww < 8; ww++) s += part_s[t * 8 + ww];
            inv_s[t] = 1.0f / s;
        }
        __syncthreads();

        // Phase 3a: raw (e*V) @ [Wmu|Wvar], packed FFMA2; thread owns 1 output
        // col over a 64-wide k-partition (weights loaded once, reused x16 rows)
        {
            const int c  = t & 63;
            const int kp = t >> 6;
            const float* Wcol = (c < 32) ? (Wmu + c) : (Wvar + (c - 32));
            u64 acc2[16];
            #pragma unroll
            for (int m = 0; m < 16; m++) acc2[m] = 0ull;
            const int k0 = kp * 64;
            #pragma unroll 2
            for (int k = k0; k < k0 + 64; k += 4) {
                float w0 = Wcol[(size_t)(k+0)*COMP], w1 = Wcol[(size_t)(k+1)*COMP];
                float w2 = Wcol[(size_t)(k+2)*COMP], w3 = Wcol[(size_t)(k+3)*COMP];
                u64 w01 = pk(w0, w1), w23 = pk(w2, w3);
                #pragma unroll
                for (int m = 0; m < 16; m++) {
                    u64 a01, a23;
                    lds2(a01, a23, ha_sa + (unsigned)((m * HID + k) * 4));
                    ffma2(acc2[m], a01, w01); ffma2(acc2[m], a23, w23);
                }
            }
            __syncthreads();   // all ha_s reads done -> reuse as staging
            #pragma unroll
            for (int m = 0; m < 16; m++) ha_s[kp * 1024 + m * 64 + c] = upk_sum(acc2[m]);
        }
        __syncthreads();
        // reduce 4 k-partitions -> mulv_s[m][c]
        {
            float4 s = ((const float4*)ha_s)[t];
            #pragma unroll
            for (int kp = 1; kp < 4; kp++) {
                float4 b = ((const float4*)ha_s)[kp * 256 + t];
                s.x += b.x; s.y += b.y; s.z += b.z; s.w += b.w;
            }
            ((float4*)mulv_s)[t] = s;
        }
        __syncthreads();

        // Phase 3b: normalize, bias, sample, nearest-vocab sq dist, mask
        {
            const int m  = t >> 4;
            const int c0 = (t & 15) * 2;
            const float iv = inv_s[m];
            float2 rmu = *(const float2*)&mulv_s[m * 64 + c0];
            float2 rlv = *(const float2*)&mulv_s[m * 64 + 32 + c0];
            float2 bm  = *(const float2*)&bmu[c0];
            float2 bv  = *(const float2*)&bvar[c0];
            float amu0 = rmu.x * iv + bm.x, amu1 = rmu.y * iv + bm.y;
            float alv0 = rlv.x * iv + bv.x, alv1 = rlv.y * iv + bv.y;
            const size_t r = (size_t)(r0 + m);
            const float* ep = eps + ((size_t)it * B_ROWS + r) * COMP + c0;
            float2 e2 = *(const float2*)ep;
            float x0 = e2.x * __expf(0.5f * alv0) + amu0;
            float x1 = e2.y * __expf(0.5f * alv1) + amu1;
            float d0 = nearest_sq(vocs_s + c0 * VSTRIDE, x0);
            float d1 = nearest_sq(vocs_s + (c0 + 1) * VSTRIDE, x1);
            const float mk = maskf[m];
            tok_s[m * COMP + c0]     = d0 * mk;
            tok_s[m * COMP + c0 + 1] = d1 * mk;
        }
        __syncthreads();

        // Phase 4: EOS / repeat-hit logic -> final token into tok_s + msg_s
        {
            #pragma unroll
            for (int mm = 0; mm < 2; mm++) {
                const int m = w * 2 + mm;
                float tk = tok_s[m * COMP + l];
                float ev = eos_s[l];
                float de = tk - ev;
                float se = de * de;
                #pragma unroll
                for (int o = 16; o; o >>= 1) se += __shfl_xor_sync(0xffffffffu, se, o);
                bool hit = (se < EPS_THR);
                for (int p = 0; p < it; p++) {
                    float dp = tk - msg_s[m * HID + p * COMP + l];
                    float sp = dp * dp;
                    #pragma unroll
                    for (int o = 16; o; o >>= 1) sp += __shfl_xor_sync(0xffffffffu, sp, o);
                    hit = hit || (sp < EPS_THR);
                }
                float fin = fin_s[m];
                bool new_eos = hit && (fin == 0.0f);
                float outv = new_eos ? ev : tk;
                msg_s[m * HID + it * COMP + l] = outv;
                tok_s[m * COMP + l] = outv;
                if (l == 0 && hit) { maskf[m] = 0.0f; fin_s[m] = 1.0f; }
            }
        }
    }

    // ---- flush message to global for the tail ----
    __syncthreads();
    {
        float4* dst = (float4*)(g_msg + (size_t)r0 * HID);
        const float4* src = (const float4*)msg_s;
        for (int i = t; i < ROWS_PB * HID / 4; i += 256) dst[i] = src[i];
    }
}

// ---------------- Kernel 2: fused tail: group-sum/7 @Wsum -> @Whead+relu ---
__global__ __launch_bounds__(256) void tail_kernel(
    const float* __restrict__ Wsum, const float* __restrict__ bsum,
    const float* __restrict__ Whead, const float* __restrict__ bhead,
    float* __restrict__ out)
{
    __shared__ __align__(16) float A_s[16 * HID];
    const int t = threadIdx.x;
    const int g0 = blockIdx.x * 16;
    const unsigned A_sa = (unsigned)__cvta_generic_to_shared(A_s);

    #pragma unroll
    for (int m = 0; m < 16; m++) {
        float s = 0.0f;
        #pragma unroll
        for (int a = 0; a < 8; a++)
            s += g_msg[(size_t)((g0 + m) * 8 + a) * HID + t];
        A_s[m * HID + t] = s * (1.0f / 7.0f);
    }
    __syncthreads();

    float res[16];
    {
        u64 acc2[16];
        const float bb = bsum[t];
        #pragma unroll
        for (int m = 0; m < 16; m++) acc2[m] = pk(bb, 0.0f);
        #pragma unroll 2
        for (int k = 0; k < HID; k += 4) {
            float w0 = Wsum[(k+0)*HID+t], w1 = Wsum[(k+1)*HID+t];
            float w2 = Wsum[(k+2)*HID+t], w3 = Wsum[(k+3)*HID+t];
            u64 w01 = pk(w0, w1), w23 = pk(w2, w3);
            #pragma unroll
            for (int m = 0; m < 16; m++) {
                u64 a01, a23;
                lds2(a01, a23, A_sa + (unsigned)((m * HID + k) * 4));
                ffma2(acc2[m], a01, w01); ffma2(acc2[m], a23, w23);
            }
        }
        #pragma unroll
        for (int m = 0; m < 16; m++) res[m] = upk_sum(acc2[m]);
    }
    __syncthreads();
    #pragma unroll
    for (int m = 0; m < 16; m++) A_s[m * HID + t] = res[m];
    __syncthreads();

    {
        u64 acc2[16];
        const float bb = bhead[t];
        #pragma unroll
        for (int m = 0; m < 16; m++) acc2[m] = pk(bb, 0.0f);
        #pragma unroll 2
        for (int k = 0; k < HID; k += 4) {
            float w0 = Whead[(k+0)*HID+t], w1 = Whead[(k+1)*HID+t];
            float w2 = Whead[(k+2)*HID+t], w3 = Whead[(k+3)*HID+t];
            u64 w01 = pk(w0, w1), w23 = pk(w2, w3);
            #pragma unroll
            for (int m = 0; m < 16; m++) {
                u64 a01, a23;
                lds2(a01, a23, A_sa + (unsigned)((m * HID + k) * 4));
                ffma2(acc2[m], a01, w01); ffma2(acc2[m], a23, w23);
            }
        }
        #pragma unroll
        for (int m = 0; m < 16; m++) res[m] = upk_sum(acc2[m]);
    }
    #pragma unroll
    for (int m = 0; m < 16; m++) {
        float v = fmaxf(res[m], 0.0f);
        #pragma unroll
        for (int a = 0; a < 8; a++)
            out[(size_t)((g0 + m) * 8 + a) * HID + t] = v;
    }
}

// ---------------- launch ---------------------------------------------------
extern "C" void kernel_launch(void* const* d_in, const int* in_sizes, int n_in,
                              void* d_out, int out_size)
{
    const float* hs    = (const float*)d_in[0];
    const float* eps   = (const float*)d_in[1];
    const float* WQ    = (const float*)d_in[2];
    const float* bQ    = (const float*)d_in[3];
    const float* WK    = (const float*)d_in[4];
    const float* bK    = (const float*)d_in[5];
    const float* Wmu   = (const float*)d_in[6];
    const float* bmu   = (const float*)d_in[7];
    const float* Wvar  = (const float*)d_in[8];
    const float* bvar  = (const float*)d_in[9];
    const float* vocab = (const float*)d_in[10];
    const float* Wsum  = (const float*)d_in[11];
    const float* bsum  = (const float*)d_in[12];
    const float* Whead = (const float*)d_in[13];
    const float* bhead = (const float*)d_in[14];
    float* out = (float*)d_out;

    const int smem_main = 18288 * (int)sizeof(float);   // 73152 B
    cudaFuncSetAttribute(main_kernel,
                         cudaFuncAttributeMaxDynamicSharedMemorySize, smem_main);

    sort_kernel<<<COMP, 512>>>(vocab);
    main_kernel<<<B_ROWS / ROWS_PB, 256, smem_main>>>(
        hs, WQ, bQ, WK, bK, Wmu, bmu, Wvar, bvar, vocab, eps);
    tail_kernel<<<NGROUP / 16, 256>>>(Wsum, bsum, Whead, bhead, out);
}